// round 1
// baseline (speedup 1.0000x reference)
#include <cuda_runtime.h>
#include <math.h>

#define BATCH 8
#define NTOK  1024
#define CDIM  768
#define NHEAD 12
#define HDIM  64
#define NTOTC 2304   // 768 (Q) + 1536 (KV)
#define MROWS 8192   // BATCH * NTOK

// -------- scratch (device globals: no allocations allowed) --------
__device__ float g_q[BATCH * NHEAD * NTOK * HDIM];
__device__ float g_k[BATCH * NHEAD * NTOK * HDIM];
__device__ float g_v[BATCH * NHEAD * NTOK * HDIM];

// ============================================================================
// Kernel 1: fused QKV projection.
//   Q  = (x @ Wq^T  + bq) * 0.125   -> g_q[b][h][n][d]
//   K  = (x @ Wkv^T + bkv)[:, 0:768]   -> g_k
//   V  = (x @ Wkv^T + bkv)[:, 768:1536]-> g_v
// Both operands row-major, dot over the contiguous dim (NT-GEMM).
// 128x128x8 tiles, 256 threads, 8x8 microtile (4+4 split cols/rows).
// ============================================================================
__global__ __launch_bounds__(256, 2)
void qkv_gemm(const float* __restrict__ x,
              const float* __restrict__ Wq,  const float* __restrict__ bq,
              const float* __restrict__ Wkv, const float* __restrict__ bkv)
{
    __shared__ float As[8][128];
    __shared__ float Bs[8][128];

    const int tid = threadIdx.x;
    const int tx  = tid & 15;
    const int ty  = tid >> 4;
    const int mBase = blockIdx.y * 128;
    const int nBase = blockIdx.x * 128;

    // Loader mapping: each thread loads one float4 for A and one for B per K-step.
    const int lr = tid >> 1;        // 0..127 tile row
    const int lk = (tid & 1) * 4;   // 0 or 4

    const float* Aptr = x + (size_t)(mBase + lr) * CDIM + lk;
    const int cGlob = nBase + lr;
    const float* Bptr = (cGlob < CDIM) ? (Wq + (size_t)cGlob * CDIM + lk)
                                       : (Wkv + (size_t)(cGlob - CDIM) * CDIM + lk);

    float acc[8][8];
#pragma unroll
    for (int i = 0; i < 8; i++)
#pragma unroll
        for (int j = 0; j < 8; j++) acc[i][j] = 0.f;

    float4 aReg = *(const float4*)Aptr;
    float4 bReg = *(const float4*)Bptr;

    for (int k0 = 0; k0 < CDIM; k0 += 8) {
        As[lk + 0][lr] = aReg.x; As[lk + 1][lr] = aReg.y;
        As[lk + 2][lr] = aReg.z; As[lk + 3][lr] = aReg.w;
        Bs[lk + 0][lr] = bReg.x; Bs[lk + 1][lr] = bReg.y;
        Bs[lk + 2][lr] = bReg.z; Bs[lk + 3][lr] = bReg.w;
        __syncthreads();

        if (k0 + 8 < CDIM) {
            aReg = *(const float4*)(Aptr + k0 + 8);
            bReg = *(const float4*)(Bptr + k0 + 8);
        }

#pragma unroll
        for (int kk = 0; kk < 8; kk++) {
            float4 a0 = *(const float4*)&As[kk][ty * 4];
            float4 a1 = *(const float4*)&As[kk][64 + ty * 4];
            float4 b0 = *(const float4*)&Bs[kk][tx * 4];
            float4 b1 = *(const float4*)&Bs[kk][64 + tx * 4];
            float a[8] = {a0.x, a0.y, a0.z, a0.w, a1.x, a1.y, a1.z, a1.w};
            float b[8] = {b0.x, b0.y, b0.z, b0.w, b1.x, b1.y, b1.z, b1.w};
#pragma unroll
            for (int i = 0; i < 8; i++)
#pragma unroll
                for (int j = 0; j < 8; j++) acc[i][j] = fmaf(a[i], b[j], acc[i][j]);
        }
        __syncthreads();
    }

    // Epilogue: route column groups into g_q / g_k / g_v with (B,NH,N,HD) layout.
#pragma unroll
    for (int jg = 0; jg < 2; jg++) {
        const int cBase = nBase + jg * 64 + tx * 4;   // 4 consecutive cols, same head
        float4 bv;
        float mul = 1.f;
        float* base;
        if (cBase < 768)       { bv = *(const float4*)(bq + cBase);          base = g_q; mul = 0.125f; }
        else if (cBase < 1536) { bv = *(const float4*)(bkv + (cBase - 768)); base = g_k; }
        else                   { bv = *(const float4*)(bkv + (cBase - 768)); base = g_v; }
        const int cc = cBase % 768;
        const int hh = cc >> 6;       // head
        const int dd = cc & 63;       // dim within head
#pragma unroll
        for (int ig = 0; ig < 2; ig++) {
#pragma unroll
            for (int i = 0; i < 4; i++) {
                const int m    = mBase + ig * 64 + ty * 4 + i;  // global token row
                const int bidx = m >> 10;
                const int ntok = m & 1023;
                float4 r;
                r.x = (acc[ig * 4 + i][jg * 4 + 0] + bv.x) * mul;
                r.y = (acc[ig * 4 + i][jg * 4 + 1] + bv.y) * mul;
                r.z = (acc[ig * 4 + i][jg * 4 + 2] + bv.z) * mul;
                r.w = (acc[ig * 4 + i][jg * 4 + 3] + bv.w) * mul;
                *(float4*)&base[(size_t)(((bidx * NHEAD + hh) * NTOK + ntok)) * HDIM + dd] = r;
            }
        }
    }
}

// ============================================================================
// Kernel 2: flash attention with fused Swin relative-position bias.
// Grid: (8 q-tiles, 96 b*h). Block: 256 threads (16x16).
// Q tile 128x64 resident (transposed). 16 K/V tiles of 64 keys each.
// Score microtile per thread: 8 rows (4+4 split) x 4 cols.
// Bias computed arithmetically: idx = (qi-ki+31)*63 + (qj-kj+31).
// ============================================================================
#define QS_STRIDE 132
#define KS_STRIDE 68
#define VS_STRIDE 68
#define PS_STRIDE 72
#define FLASH_SMEM_FLOATS (64*QS_STRIDE + 64*KS_STRIDE + 64*VS_STRIDE + 128*PS_STRIDE)
#define FLASH_SMEM_BYTES  (FLASH_SMEM_FLOATS * 4)

__global__ __launch_bounds__(256, 2)
void flash_attn(const float* __restrict__ rel_bias, float* __restrict__ out)
{
    extern __shared__ float smem[];
    float* Qs = smem;                       // [64][132]  Qs[d][m]
    float* Ks = Qs + 64 * QS_STRIDE;        // [64][68]   Ks[d][n]
    float* Vs = Ks + 64 * KS_STRIDE;        // [64][68]   Vs[n][d]
    float* Ps = Vs + 64 * VS_STRIDE;        // [128][72]  Ps[m][n]

    const int tid = threadIdx.x;
    const int tx  = tid & 15;
    const int ty  = tid >> 4;
    const int qt  = blockIdx.x;             // 0..7
    const int bh  = blockIdx.y;             // 0..95
    const int b   = bh / NHEAD;
    const int h   = bh % NHEAD;

    const float* qbase = g_q + (size_t)bh * NTOK * HDIM + (size_t)qt * 128 * HDIM;
    const float* kbase = g_k + (size_t)bh * NTOK * HDIM;
    const float* vbase = g_v + (size_t)bh * NTOK * HDIM;

    // ---- load Q tile (128x64), transposed into Qs[d][m] ----
    {
        const int m  = tid >> 1;
        const int dq = (tid & 1) * 4;
#pragma unroll
        for (int it = 0; it < 8; it++) {
            const int d = it * 8 + dq;
            float4 v = *(const float4*)&qbase[m * HDIM + d];
            Qs[(d + 0) * QS_STRIDE + m] = v.x;
            Qs[(d + 1) * QS_STRIDE + m] = v.y;
            Qs[(d + 2) * QS_STRIDE + m] = v.z;
            Qs[(d + 3) * QS_STRIDE + m] = v.w;
        }
    }

    // per-thread row indices (8 rows: 4+4 split)
    int rowIdx[8];
#pragma unroll
    for (int i = 0; i < 8; i++)
        rowIdx[i] = (i < 4) ? (ty * 4 + i) : (64 + ty * 4 + (i - 4));

    // precompute q spatial coords for bias
    int qi[8], qj[8];
#pragma unroll
    for (int i = 0; i < 8; i++) {
        const int qg = qt * 128 + rowIdx[i];
        qi[i] = qg >> 5;
        qj[i] = qg & 31;
    }

    float o[8][4];
#pragma unroll
    for (int i = 0; i < 8; i++)
#pragma unroll
        for (int j = 0; j < 4; j++) o[i][j] = 0.f;
    float mrow[8], lrow[8];
#pragma unroll
    for (int i = 0; i < 8; i++) { mrow[i] = -INFINITY; lrow[i] = 0.f; }

    const int ldN = tid >> 2;              // 0..63 (K/V loader row)
    const int ldD = (tid & 3) * 4;         // 0,4,8,12

    for (int kt = 0; kt < 16; kt++) {
        __syncthreads();   // previous iteration's smem consumers done

        // ---- load K (transposed) and V tiles ----
#pragma unroll
        for (int it = 0; it < 4; it++) {
            const int d = it * 16 + ldD;
            float4 kv4 = *(const float4*)&kbase[(kt * 64 + ldN) * HDIM + d];
            Ks[(d + 0) * KS_STRIDE + ldN] = kv4.x;
            Ks[(d + 1) * KS_STRIDE + ldN] = kv4.y;
            Ks[(d + 2) * KS_STRIDE + ldN] = kv4.z;
            Ks[(d + 3) * KS_STRIDE + ldN] = kv4.w;
            float4 vv4 = *(const float4*)&vbase[(kt * 64 + ldN) * HDIM + d];
            *(float4*)&Vs[ldN * VS_STRIDE + d] = vv4;
        }
        __syncthreads();

        // ---- scores S = Q K^T (128x64 tile; thread: 8x4) ----
        float s[8][4];
#pragma unroll
        for (int i = 0; i < 8; i++)
#pragma unroll
            for (int j = 0; j < 4; j++) s[i][j] = 0.f;

#pragma unroll 8
        for (int d = 0; d < 64; d++) {
            float4 a0 = *(const float4*)&Qs[d * QS_STRIDE + ty * 4];
            float4 a1 = *(const float4*)&Qs[d * QS_STRIDE + 64 + ty * 4];
            float4 bb = *(const float4*)&Ks[d * KS_STRIDE + tx * 4];
            float a[8] = {a0.x, a0.y, a0.z, a0.w, a1.x, a1.y, a1.z, a1.w};
            float bv[4] = {bb.x, bb.y, bb.z, bb.w};
#pragma unroll
            for (int i = 0; i < 8; i++)
#pragma unroll
                for (int j = 0; j < 4; j++) s[i][j] = fmaf(a[i], bv[j], s[i][j]);
        }

        // ---- add relative-position bias (arithmetic index) ----
        int ki[4], kj[4];
#pragma unroll
        for (int j = 0; j < 4; j++) {
            const int kg = kt * 64 + tx * 4 + j;
            ki[j] = kg >> 5;
            kj[j] = kg & 31;
        }
#pragma unroll
        for (int i = 0; i < 8; i++)
#pragma unroll
            for (int j = 0; j < 4; j++) {
                const int idx = (qi[i] - ki[j] + 31) * 63 + (qj[i] - kj[j] + 31);
                s[i][j] += __ldg(&rel_bias[idx * NHEAD + h]);
            }

        // ---- online softmax update ----
#pragma unroll
        for (int i = 0; i < 8; i++) {
            float mx = fmaxf(fmaxf(s[i][0], s[i][1]), fmaxf(s[i][2], s[i][3]));
#pragma unroll
            for (int off = 1; off < 16; off <<= 1)
                mx = fmaxf(mx, __shfl_xor_sync(0xffffffffu, mx, off));
            const float mnew  = fmaxf(mrow[i], mx);
            const float alpha = __expf(mrow[i] - mnew);
            float rs = 0.f;
#pragma unroll
            for (int j = 0; j < 4; j++) {
                const float p = __expf(s[i][j] - mnew);
                s[i][j] = p;
                rs += p;
            }
#pragma unroll
            for (int off = 1; off < 16; off <<= 1)
                rs += __shfl_xor_sync(0xffffffffu, rs, off);
            lrow[i] = lrow[i] * alpha + rs;
            mrow[i] = mnew;
#pragma unroll
            for (int j = 0; j < 4; j++) o[i][j] *= alpha;
        }

        // ---- write P to smem for the PV GEMM ----
#pragma unroll
        for (int i = 0; i < 8; i++) {
            float4 p4 = make_float4(s[i][0], s[i][1], s[i][2], s[i][3]);
            *(float4*)&Ps[rowIdx[i] * PS_STRIDE + tx * 4] = p4;
        }
        __syncthreads();

        // ---- O += P @ V ----
#pragma unroll 4
        for (int k = 0; k < 64; k++) {
            float4 vv = *(const float4*)&Vs[k * VS_STRIDE + tx * 4];
            float pf[8];
#pragma unroll
            for (int i = 0; i < 8; i++) pf[i] = Ps[rowIdx[i] * PS_STRIDE + k];
#pragma unroll
            for (int i = 0; i < 8; i++) {
                o[i][0] = fmaf(pf[i], vv.x, o[i][0]);
                o[i][1] = fmaf(pf[i], vv.y, o[i][1]);
                o[i][2] = fmaf(pf[i], vv.z, o[i][2]);
                o[i][3] = fmaf(pf[i], vv.w, o[i][3]);
            }
        }
    }

    // ---- epilogue: normalize and write out (B, N, C) ----
#pragma unroll
    for (int i = 0; i < 8; i++) {
        const float inv = 1.f / lrow[i];
        const int qg = qt * 128 + rowIdx[i];
        float4 r = make_float4(o[i][0] * inv, o[i][1] * inv, o[i][2] * inv, o[i][3] * inv);
        *(float4*)&out[(size_t)(b * NTOK + qg) * CDIM + h * HDIM + tx * 4] = r;
    }
}

// ============================================================================
extern "C" void kernel_launch(void* const* d_in, const int* in_sizes, int n_in,
                              void* d_out, int out_size)
{
    const float* x        = (const float*)d_in[0];
    const float* Wq       = (const float*)d_in[1];
    const float* bq       = (const float*)d_in[2];
    const float* Wkv      = (const float*)d_in[3];
    const float* bkv      = (const float*)d_in[4];
    const float* rel_bias = (const float*)d_in[5];
    float* out = (float*)d_out;

    qkv_gemm<<<dim3(NTOTC / 128, MROWS / 128), 256>>>(x, Wq, bq, Wkv, bkv);

    cudaFuncSetAttribute(flash_attn, cudaFuncAttributeMaxDynamicSharedMemorySize,
                         FLASH_SMEM_BYTES);
    flash_attn<<<dim3(8, BATCH * NHEAD), 256, FLASH_SMEM_BYTES>>>(rel_bias, out);
}

// round 3
// speedup vs baseline: 2.1096x; 2.1096x over previous
#include <cuda_runtime.h>
#include <math.h>
#include <stdint.h>

#define BATCH 8
#define NTOK  1024
#define CDIM  768
#define NHEAD 12
#define HDIM  64
#define NTOTC 2304   // 768 (Q) + 1536 (KV)
#define MROWS 8192   // BATCH * NTOK

// -------- scratch (device globals: no allocations allowed) --------
__device__ float g_q[BATCH * NHEAD * NTOK * HDIM];
__device__ float g_k[BATCH * NHEAD * NTOK * HDIM];
__device__ float g_v[BATCH * NHEAD * NTOK * HDIM];

// ============================================================================
// helpers
// ============================================================================
__device__ __forceinline__ uint32_t f2tf32(float x) {
    uint32_t r;
    asm("cvt.rna.tf32.f32 %0, %1;" : "=r"(r) : "f"(x));
    return r;
}

// D += A(16x8) * B(8x8), tf32 inputs, f32 accumulate. d is C and D.
__device__ __forceinline__ void mma8(float4& d,
                                     uint32_t a0, uint32_t a1, uint32_t a2, uint32_t a3,
                                     uint32_t b0, uint32_t b1) {
    asm volatile(
        "mma.sync.aligned.m16n8k8.row.col.f32.tf32.tf32.f32 "
        "{%0,%1,%2,%3}, {%4,%5,%6,%7}, {%8,%9}, {%0,%1,%2,%3};"
        : "+f"(d.x), "+f"(d.y), "+f"(d.z), "+f"(d.w)
        : "r"(a0), "r"(a1), "r"(a2), "r"(a3), "r"(b0), "r"(b1));
}

// ============================================================================
// Kernel 1: fused QKV projection, tf32 mma.sync.
//   out[m][n] = sum_k x[m][k]*W[n][k] (+bias; Q scaled by 0.125)
// CTA tile 128(M)x128(N), 8 warps as 4(M)x2(N) -> warp tile 32x64.
// K in 24 chunks of 32, register prefetch double-buffer.
// ============================================================================
#define ASTR 36
__global__ __launch_bounds__(256)
void qkv_tc(const float* __restrict__ x,
            const float* __restrict__ Wq,  const float* __restrict__ bq,
            const float* __restrict__ Wkv, const float* __restrict__ bkv)
{
    __shared__ uint32_t As[128][ASTR];
    __shared__ uint32_t Bs[128][ASTR];

    const int tid  = threadIdx.x;
    const int wid  = tid >> 5;
    const int lane = tid & 31;
    const int g    = lane >> 2;    // group id (row within fragment)
    const int tig  = lane & 3;     // thread in group (col)
    const int mBase = blockIdx.y * 128;
    const int nBase = blockIdx.x * 128;
    const int wm = (wid >> 1) * 32;   // warp M offset
    const int wn = (wid & 1) * 64;    // warp N offset

    // loaders: thread -> row tid>>1, 16 cols at (tid&1)*16
    const int lrow  = tid >> 1;
    const int lcol0 = (tid & 1) * 16;
    const float* Ag = x + (size_t)(mBase + lrow) * CDIM + lcol0;
    const int nrow = nBase + lrow;
    const float* Bg = (nrow < CDIM) ? (Wq + (size_t)nrow * CDIM + lcol0)
                                    : (Wkv + (size_t)(nrow - CDIM) * CDIM + lcol0);

    float4 ar[4], br[4];
#pragma unroll
    for (int i = 0; i < 4; i++) {
        ar[i] = *(const float4*)(Ag + 4 * i);
        br[i] = *(const float4*)(Bg + 4 * i);
    }

    float4 dacc[2][8];
#pragma unroll
    for (int mt = 0; mt < 2; mt++)
#pragma unroll
        for (int nt = 0; nt < 8; nt++) dacc[mt][nt] = make_float4(0.f, 0.f, 0.f, 0.f);

    for (int ch = 0; ch < 24; ch++) {
        // store current chunk (tf32-converted)
#pragma unroll
        for (int i = 0; i < 4; i++) {
            uint32_t* pa = &As[lrow][lcol0 + 4 * i];
            pa[0] = f2tf32(ar[i].x); pa[1] = f2tf32(ar[i].y);
            pa[2] = f2tf32(ar[i].z); pa[3] = f2tf32(ar[i].w);
            uint32_t* pb = &Bs[lrow][lcol0 + 4 * i];
            pb[0] = f2tf32(br[i].x); pb[1] = f2tf32(br[i].y);
            pb[2] = f2tf32(br[i].z); pb[3] = f2tf32(br[i].w);
        }
        __syncthreads();

        if (ch < 23) {
#pragma unroll
            for (int i = 0; i < 4; i++) {
                ar[i] = *(const float4*)(Ag + (ch + 1) * 32 + 4 * i);
                br[i] = *(const float4*)(Bg + (ch + 1) * 32 + 4 * i);
            }
        }

#pragma unroll
        for (int ks = 0; ks < 4; ks++) {
            const int k0 = ks * 8;
            uint32_t a[2][4];
#pragma unroll
            for (int mt = 0; mt < 2; mt++) {
                const int r0 = wm + mt * 16 + g;
                a[mt][0] = As[r0][k0 + tig];
                a[mt][1] = As[r0 + 8][k0 + tig];
                a[mt][2] = As[r0][k0 + tig + 4];
                a[mt][3] = As[r0 + 8][k0 + tig + 4];
            }
#pragma unroll
            for (int nt = 0; nt < 8; nt++) {
                const int nr = wn + nt * 8 + g;
                uint32_t b0 = Bs[nr][k0 + tig];
                uint32_t b1 = Bs[nr][k0 + tig + 4];
                mma8(dacc[0][nt], a[0][0], a[0][1], a[0][2], a[0][3], b0, b1);
                mma8(dacc[1][nt], a[1][0], a[1][1], a[1][2], a[1][3], b0, b1);
            }
        }
        __syncthreads();
    }

    // ---- epilogue: bias, scale, scatter to g_q/g_k/g_v ----
    const int cb = nBase + wn;  // 64-aligned block: one dest, one head
    float mul = 1.f;
    float* basep;
    const float* brow;
    if (cb < 768)       { basep = g_q; brow = bq + cb;          mul = 0.125f; }
    else if (cb < 1536) { basep = g_k; brow = bkv + (cb - 768); }
    else                { basep = g_v; brow = bkv + (cb - 768); }
    const int hh = (cb % 768) >> 6;

#pragma unroll
    for (int mt = 0; mt < 2; mt++) {
#pragma unroll
        for (int rr = 0; rr < 2; rr++) {
            const int row = mBase + wm + mt * 16 + g + rr * 8;
            const int bidx = row >> 10;
            const int tok  = row & 1023;
            float* orow = basep + (size_t)((bidx * NHEAD + hh) * NTOK + tok) * HDIM;
#pragma unroll
            for (int nt = 0; nt < 8; nt++) {
                const int dd = nt * 8 + 2 * tig;
                float2 bias = *(const float2*)(brow + dd);
                float2 r;
                if (rr == 0) { r.x = (dacc[mt][nt].x + bias.x) * mul;
                               r.y = (dacc[mt][nt].y + bias.y) * mul; }
                else         { r.x = (dacc[mt][nt].z + bias.x) * mul;
                               r.y = (dacc[mt][nt].w + bias.y) * mul; }
                *(float2*)(orow + dd) = r;
            }
        }
    }
}

// ============================================================================
// Kernel 2: flash attention, tf32 mma.sync, fused Swin relative bias.
// Grid (8 q-tiles, 96 b*h), 256 threads (8 warps).
// Warp owns 16 q-rows x all 64 kv-cols (softmax reduce stays in-quad).
// P relayout C-frag -> A-frag via warp-local smem (syncwarp only).
// ============================================================================
#define QSTR 68
#define KSTR 68
#define VSTR 72
#define PSTR 68
#define FL_QS 0
#define FL_KS (FL_QS + 128 * QSTR)
#define FL_VS (FL_KS + 64 * KSTR)
#define FL_PS (FL_VS + 64 * VSTR)
#define FL_WORDS (FL_PS + 128 * PSTR)
#define FL_BYTES (FL_WORDS * 4)

__global__ __launch_bounds__(256)
void flash_tc(const float* __restrict__ rel_bias, float* __restrict__ out)
{
    extern __shared__ uint32_t sm[];
    uint32_t* Qs = sm + FL_QS;   // [128][QSTR] tf32, [m][d]
    uint32_t* Ks = sm + FL_KS;   // [64][KSTR]  tf32, [kv][d]
    uint32_t* Vs = sm + FL_VS;   // [64][VSTR]  tf32, [kv][d]
    uint32_t* Ps = sm + FL_PS;   // [128][PSTR] tf32, [m][kv]

    const int tid  = threadIdx.x;
    const int wid  = tid >> 5;
    const int lane = tid & 31;
    const int g    = lane >> 2;
    const int tig  = lane & 3;
    const int qt   = blockIdx.x;
    const int bh   = blockIdx.y;
    const int b    = bh / NHEAD;
    const int h    = bh % NHEAD;

    const float* qbase = g_q + (size_t)bh * NTOK * HDIM + (size_t)qt * 128 * HDIM;
    const float* kbase = g_k + (size_t)bh * NTOK * HDIM;
    const float* vbase = g_v + (size_t)bh * NTOK * HDIM;

    // ---- load Q tile 128x64 -> tf32 smem ----
    {
        const int row = tid >> 1;
        const int c0  = (tid & 1) * 32;
#pragma unroll
        for (int i = 0; i < 8; i++) {
            float4 v = *(const float4*)(qbase + row * HDIM + c0 + 4 * i);
            uint32_t* p = &Qs[row * QSTR + c0 + 4 * i];
            p[0] = f2tf32(v.x); p[1] = f2tf32(v.y);
            p[2] = f2tf32(v.z); p[3] = f2tf32(v.w);
        }
    }

    const int qr = wid * 16;                   // warp's q-row base (local)
    const int qrow0 = qt * 128 + qr + g;       // global q row (and +8)
    const int qi0 = qrow0 >> 5,       qj0 = qrow0 & 31;
    const int qi1 = (qrow0 + 8) >> 5, qj1 = (qrow0 + 8) & 31;

    float4 o[8];
#pragma unroll
    for (int nt = 0; nt < 8; nt++) o[nt] = make_float4(0.f, 0.f, 0.f, 0.f);
    float m0 = -INFINITY, m1 = -INFINITY, l0 = 0.f, l1 = 0.f;

    const int ldRow = tid >> 2;
    const int ldC0  = (tid & 3) * 16;

    for (int kt = 0; kt < 16; kt++) {
        __syncthreads();   // prior S/PV consumers of Ks/Vs done (also guards Qs at kt=0)

        // ---- load K,V tile 64x64 each ----
#pragma unroll
        for (int i = 0; i < 4; i++) {
            const int c = ldC0 + 4 * i;
            float4 kv4 = *(const float4*)(kbase + (kt * 64 + ldRow) * HDIM + c);
            uint32_t* pk = &Ks[ldRow * KSTR + c];
            pk[0] = f2tf32(kv4.x); pk[1] = f2tf32(kv4.y);
            pk[2] = f2tf32(kv4.z); pk[3] = f2tf32(kv4.w);
            float4 vv4 = *(const float4*)(vbase + (kt * 64 + ldRow) * HDIM + c);
            uint32_t* pv = &Vs[ldRow * VSTR + c];
            pv[0] = f2tf32(vv4.x); pv[1] = f2tf32(vv4.y);
            pv[2] = f2tf32(vv4.z); pv[3] = f2tf32(vv4.w);
        }
        __syncthreads();

        // ---- S = Q K^T (warp: 16x64) ----
        float4 s[8];
#pragma unroll
        for (int nt = 0; nt < 8; nt++) s[nt] = make_float4(0.f, 0.f, 0.f, 0.f);
#pragma unroll
        for (int ks = 0; ks < 8; ks++) {
            const int k0 = ks * 8;
            uint32_t a0 = Qs[(qr + g) * QSTR + k0 + tig];
            uint32_t a1 = Qs[(qr + g + 8) * QSTR + k0 + tig];
            uint32_t a2 = Qs[(qr + g) * QSTR + k0 + tig + 4];
            uint32_t a3 = Qs[(qr + g + 8) * QSTR + k0 + tig + 4];
#pragma unroll
            for (int nt = 0; nt < 8; nt++) {
                uint32_t b0 = Ks[(nt * 8 + g) * KSTR + k0 + tig];
                uint32_t b1 = Ks[(nt * 8 + g) * KSTR + k0 + tig + 4];
                mma8(s[nt], a0, a1, a2, a3, b0, b1);
            }
        }

        // ---- bias + row max ----
        float mx0 = -INFINITY, mx1 = -INFINITY;
#pragma unroll
        for (int nt = 0; nt < 8; nt++) {
            const int col0 = kt * 64 + nt * 8 + 2 * tig;  // even; col1 same 32-block
            const int ki = col0 >> 5;
            const int kj = col0 & 31;
            s[nt].x += __ldg(&rel_bias[((qi0 - ki + 31) * 63 + (qj0 - kj + 31)) * NHEAD + h]);
            s[nt].y += __ldg(&rel_bias[((qi0 - ki + 31) * 63 + (qj0 - kj + 30)) * NHEAD + h]);
            s[nt].z += __ldg(&rel_bias[((qi1 - ki + 31) * 63 + (qj1 - kj + 31)) * NHEAD + h]);
            s[nt].w += __ldg(&rel_bias[((qi1 - ki + 31) * 63 + (qj1 - kj + 30)) * NHEAD + h]);
            mx0 = fmaxf(mx0, fmaxf(s[nt].x, s[nt].y));
            mx1 = fmaxf(mx1, fmaxf(s[nt].z, s[nt].w));
        }
        mx0 = fmaxf(mx0, __shfl_xor_sync(0xffffffffu, mx0, 1));
        mx0 = fmaxf(mx0, __shfl_xor_sync(0xffffffffu, mx0, 2));
        mx1 = fmaxf(mx1, __shfl_xor_sync(0xffffffffu, mx1, 1));
        mx1 = fmaxf(mx1, __shfl_xor_sync(0xffffffffu, mx1, 2));

        const float mn0 = fmaxf(m0, mx0);
        const float mn1 = fmaxf(m1, mx1);
        const float al0 = __expf(m0 - mn0);
        const float al1 = __expf(m1 - mn1);
        float rs0 = 0.f, rs1 = 0.f;
#pragma unroll
        for (int nt = 0; nt < 8; nt++) {
            s[nt].x = __expf(s[nt].x - mn0);
            s[nt].y = __expf(s[nt].y - mn0);
            s[nt].z = __expf(s[nt].z - mn1);
            s[nt].w = __expf(s[nt].w - mn1);
            rs0 += s[nt].x + s[nt].y;
            rs1 += s[nt].z + s[nt].w;
            o[nt].x *= al0; o[nt].y *= al0;
            o[nt].z *= al1; o[nt].w *= al1;
        }
        rs0 += __shfl_xor_sync(0xffffffffu, rs0, 1);
        rs0 += __shfl_xor_sync(0xffffffffu, rs0, 2);
        rs1 += __shfl_xor_sync(0xffffffffu, rs1, 1);
        rs1 += __shfl_xor_sync(0xffffffffu, rs1, 2);
        l0 = l0 * al0 + rs0; m0 = mn0;
        l1 = l1 * al1 + rs1; m1 = mn1;

        // ---- P to warp-local smem (C-frag -> A-frag relayout) ----
#pragma unroll
        for (int nt = 0; nt < 8; nt++) {
            uint32_t* p0 = &Ps[(qr + g) * PSTR + nt * 8 + 2 * tig];
            p0[0] = f2tf32(s[nt].x); p0[1] = f2tf32(s[nt].y);
            uint32_t* p1 = &Ps[(qr + g + 8) * PSTR + nt * 8 + 2 * tig];
            p1[0] = f2tf32(s[nt].z); p1[1] = f2tf32(s[nt].w);
        }
        __syncwarp();

        // ---- O += P V ----
#pragma unroll
        for (int ks = 0; ks < 8; ks++) {
            const int k0 = ks * 8;
            uint32_t a0 = Ps[(qr + g) * PSTR + k0 + tig];
            uint32_t a1 = Ps[(qr + g + 8) * PSTR + k0 + tig];
            uint32_t a2 = Ps[(qr + g) * PSTR + k0 + tig + 4];
            uint32_t a3 = Ps[(qr + g + 8) * PSTR + k0 + tig + 4];
#pragma unroll
            for (int nt = 0; nt < 8; nt++) {
                uint32_t b0 = Vs[(k0 + tig) * VSTR + nt * 8 + g];
                uint32_t b1 = Vs[(k0 + tig + 4) * VSTR + nt * 8 + g];
                mma8(o[nt], a0, a1, a2, a3, b0, b1);
            }
        }
        __syncwarp();   // PV reads done before next tile's Ps writes
    }

    // ---- epilogue ----
    const float inv0 = 1.f / l0;
    const float inv1 = 1.f / l1;
    float* out0 = out + (size_t)(b * NTOK + qrow0) * CDIM + h * HDIM;
    float* out1 = out + (size_t)(b * NTOK + qrow0 + 8) * CDIM + h * HDIM;
#pragma unroll
    for (int nt = 0; nt < 8; nt++) {
        const int dd = nt * 8 + 2 * tig;
        *(float2*)(out0 + dd) = make_float2(o[nt].x * inv0, o[nt].y * inv0);
        *(float2*)(out1 + dd) = make_float2(o[nt].z * inv1, o[nt].w * inv1);
    }
}

// ============================================================================
extern "C" void kernel_launch(void* const* d_in, const int* in_sizes, int n_in,
                              void* d_out, int out_size)
{
    const float* x        = (const float*)d_in[0];
    const float* Wq       = (const float*)d_in[1];
    const float* bq       = (const float*)d_in[2];
    const float* Wkv      = (const float*)d_in[3];
    const float* bkv      = (const float*)d_in[4];
    const float* rel_bias = (const float*)d_in[5];
    float* out = (float*)d_out;

    qkv_tc<<<dim3(NTOTC / 128, MROWS / 128), 256>>>(x, Wq, bq, Wkv, bkv);

    cudaFuncSetAttribute(flash_tc, cudaFuncAttributeMaxDynamicSharedMemorySize,
                         FL_BYTES);
    flash_tc<<<dim3(8, BATCH * NHEAD), 256, FL_BYTES>>>(rel_bias, out);
}

// round 4
// speedup vs baseline: 2.3291x; 1.1041x over previous
#include <cuda_runtime.h>
#include <math.h>
#include <stdint.h>

#define BATCH 8
#define NTOK  1024
#define CDIM  768
#define NHEAD 12
#define HDIM  64
#define NTOTC 2304   // 768 (Q) + 1536 (KV)
#define MROWS 8192   // BATCH * NTOK

// -------- scratch (device globals: no allocations allowed) --------
__device__ float g_q[BATCH * NHEAD * NTOK * HDIM];
__device__ float g_k[BATCH * NHEAD * NTOK * HDIM];
__device__ float g_v[BATCH * NHEAD * NTOK * HDIM];

// ============================================================================
// helpers
// ============================================================================
__device__ __forceinline__ uint32_t smem_u32(const void* p) {
    uint32_t a;
    asm("{ .reg .u64 t; cvta.to.shared.u64 t, %1; cvt.u32.u64 %0, t; }"
        : "=r"(a) : "l"(p));
    return a;
}
__device__ __forceinline__ uint32_t f2tf32(float x) {
    uint32_t r;
    asm("cvt.rna.tf32.f32 %0, %1;" : "=r"(r) : "f"(x));
    return r;
}
__device__ __forceinline__ void sts32(uint32_t a, uint32_t v) {
    asm volatile("st.shared.b32 [%0], %1;" :: "r"(a), "r"(v) : "memory");
}
__device__ __forceinline__ void lds64(uint32_t& x, uint32_t& y, uint32_t a) {
    asm volatile("ld.shared.v2.b32 {%0,%1}, [%2];" : "=r"(x), "=r"(y) : "r"(a));
}
__device__ __forceinline__ void lds128(uint32_t* r, uint32_t a) {
    asm volatile("ld.shared.v4.b32 {%0,%1,%2,%3}, [%4];"
                 : "=r"(r[0]), "=r"(r[1]), "=r"(r[2]), "=r"(r[3]) : "r"(a));
}

// D += A(16x8) * B(8x8), tf32 inputs, f32 accumulate.
__device__ __forceinline__ void mma8(float4& d,
                                     uint32_t a0, uint32_t a1, uint32_t a2, uint32_t a3,
                                     uint32_t b0, uint32_t b1) {
    asm volatile(
        "mma.sync.aligned.m16n8k8.row.col.f32.tf32.tf32.f32 "
        "{%0,%1,%2,%3}, {%4,%5,%6,%7}, {%8,%9}, {%0,%1,%2,%3};"
        : "+f"(d.x), "+f"(d.y), "+f"(d.z), "+f"(d.w)
        : "r"(a0), "r"(a1), "r"(a2), "r"(a3), "r"(b0), "r"(b1));
}

// ============================================================================
// Kernel 1: fused QKV projection, tf32 mma.sync (unchanged layout; 2 CTAs/SM)
// ============================================================================
#define ASTR 36
__global__ __launch_bounds__(256, 2)
void qkv_tc(const float* __restrict__ x,
            const float* __restrict__ Wq,  const float* __restrict__ bq,
            const float* __restrict__ Wkv, const float* __restrict__ bkv)
{
    __shared__ uint32_t As[128][ASTR];
    __shared__ uint32_t Bs[128][ASTR];

    const int tid  = threadIdx.x;
    const int wid  = tid >> 5;
    const int lane = tid & 31;
    const int g    = lane >> 2;
    const int tig  = lane & 3;
    const int mBase = blockIdx.y * 128;
    const int nBase = blockIdx.x * 128;
    const int wm = (wid >> 1) * 32;
    const int wn = (wid & 1) * 64;

    const int lrow  = tid >> 1;
    const int lcol0 = (tid & 1) * 16;
    const float* Ag = x + (size_t)(mBase + lrow) * CDIM + lcol0;
    const int nrow = nBase + lrow;
    const float* Bg = (nrow < CDIM) ? (Wq + (size_t)nrow * CDIM + lcol0)
                                    : (Wkv + (size_t)(nrow - CDIM) * CDIM + lcol0);

    float4 ar[4], br[4];
#pragma unroll
    for (int i = 0; i < 4; i++) {
        ar[i] = *(const float4*)(Ag + 4 * i);
        br[i] = *(const float4*)(Bg + 4 * i);
    }

    float4 dacc[2][8];
#pragma unroll
    for (int mt = 0; mt < 2; mt++)
#pragma unroll
        for (int nt = 0; nt < 8; nt++) dacc[mt][nt] = make_float4(0.f, 0.f, 0.f, 0.f);

    for (int ch = 0; ch < 24; ch++) {
#pragma unroll
        for (int i = 0; i < 4; i++) {
            uint32_t* pa = &As[lrow][lcol0 + 4 * i];
            pa[0] = f2tf32(ar[i].x); pa[1] = f2tf32(ar[i].y);
            pa[2] = f2tf32(ar[i].z); pa[3] = f2tf32(ar[i].w);
            uint32_t* pb = &Bs[lrow][lcol0 + 4 * i];
            pb[0] = f2tf32(br[i].x); pb[1] = f2tf32(br[i].y);
            pb[2] = f2tf32(br[i].z); pb[3] = f2tf32(br[i].w);
        }
        __syncthreads();

        if (ch < 23) {
#pragma unroll
            for (int i = 0; i < 4; i++) {
                ar[i] = *(const float4*)(Ag + (ch + 1) * 32 + 4 * i);
                br[i] = *(const float4*)(Bg + (ch + 1) * 32 + 4 * i);
            }
        }

#pragma unroll
        for (int ks = 0; ks < 4; ks++) {
            const int k0 = ks * 8;
            uint32_t a[2][4];
#pragma unroll
            for (int mt = 0; mt < 2; mt++) {
                const int r0 = wm + mt * 16 + g;
                a[mt][0] = As[r0][k0 + tig];
                a[mt][1] = As[r0 + 8][k0 + tig];
                a[mt][2] = As[r0][k0 + tig + 4];
                a[mt][3] = As[r0 + 8][k0 + tig + 4];
            }
#pragma unroll
            for (int nt = 0; nt < 8; nt++) {
                const int nr = wn + nt * 8 + g;
                uint32_t b0 = Bs[nr][k0 + tig];
                uint32_t b1 = Bs[nr][k0 + tig + 4];
                mma8(dacc[0][nt], a[0][0], a[0][1], a[0][2], a[0][3], b0, b1);
                mma8(dacc[1][nt], a[1][0], a[1][1], a[1][2], a[1][3], b0, b1);
            }
        }
        __syncthreads();
    }

    const int cb = nBase + wn;
    float mul = 1.f;
    float* basep;
    const float* brow;
    if (cb < 768)       { basep = g_q; brow = bq + cb;          mul = 0.125f; }
    else if (cb < 1536) { basep = g_k; brow = bkv + (cb - 768); }
    else                { basep = g_v; brow = bkv + (cb - 768); }
    const int hh = (cb % 768) >> 6;

#pragma unroll
    for (int mt = 0; mt < 2; mt++) {
#pragma unroll
        for (int rr = 0; rr < 2; rr++) {
            const int row = mBase + wm + mt * 16 + g + rr * 8;
            const int bidx = row >> 10;
            const int tok  = row & 1023;
            float* orow = basep + (size_t)((bidx * NHEAD + hh) * NTOK + tok) * HDIM;
#pragma unroll
            for (int nt = 0; nt < 8; nt++) {
                const int dd = nt * 8 + 2 * tig;
                float2 bias = *(const float2*)(brow + dd);
                float2 r;
                if (rr == 0) { r.x = (dacc[mt][nt].x + bias.x) * mul;
                               r.y = (dacc[mt][nt].y + bias.y) * mul; }
                else         { r.x = (dacc[mt][nt].z + bias.x) * mul;
                               r.y = (dacc[mt][nt].w + bias.y) * mul; }
                *(float2*)(orow + dd) = r;
            }
        }
    }
}

// ============================================================================
// Kernel 2: flash attention, tf32 mma.sync, fragment-major smem.
// Grid (8, 96), 256 threads (8 warps), warp = 16 q-rows x 64 kv-cols.
// Q A-frags register-resident (loaded once). K/V stored as B-fragments
// (LDS.64), P via bank-swizzled per-warp frag region (STS.32 / LDS.128).
// ============================================================================
#define KFB 264                       // padded K/V fragment stride (bytes)
#define KF_OFF 0
#define VF_OFF (64 * KFB)             // 16896
#define PF_OFF (2 * 64 * KFB)         // 33792
#define FL_BYTES (PF_OFF + 8 * 4096)  // 66560

__global__ __launch_bounds__(256, 2)
void flash_tc(const float* __restrict__ rel_bias, float* __restrict__ out)
{
    extern __shared__ char smraw[];
    const uint32_t sb = smem_u32(smraw);

    const int tid  = threadIdx.x;
    const int wid  = tid >> 5;
    const int lane = tid & 31;
    const int g    = lane >> 2;
    const int t    = lane & 3;
    const int qt   = blockIdx.x;
    const int bh   = blockIdx.y;
    const int b    = bh / NHEAD;
    const int h    = bh % NHEAD;

    const float* qbase = g_q + (size_t)bh * NTOK * HDIM + (size_t)qt * 128 * HDIM;
    const float* kbase = g_k + (size_t)bh * NTOK * HDIM;
    const float* vbase = g_v + (size_t)bh * NTOK * HDIM;

    // ---- Q A-fragments, register resident (one-time gmem load) ----
    const float* rp0 = qbase + (wid * 16 + g) * HDIM;
    const float* rp1 = rp0 + 8 * HDIM;
    uint32_t qf[8][4];
#pragma unroll
    for (int ks = 0; ks < 8; ks++) {
        qf[ks][0] = f2tf32(__ldg(rp0 + 8 * ks + t));
        qf[ks][1] = f2tf32(__ldg(rp1 + 8 * ks + t));
        qf[ks][2] = f2tf32(__ldg(rp0 + 8 * ks + t + 4));
        qf[ks][3] = f2tf32(__ldg(rp1 + 8 * ks + t + 4));
    }

    // ---- producer bases (all stores become [base + immediate]) ----
    // K frag (kb=k-chunk, nb): idx = g_c*4+t_c, frag = nb*8+kb
    const uint32_t Bk0 = sb + KF_OFF + (uint32_t)wid * (8 * KFB)
                       + (uint32_t)(lane >> 2) * 32 + (uint32_t)((lane & 3) * 2) * KFB;
    const uint32_t Bk1 = Bk0 + KFB;
    // V frag (kb=kv-chunk=wid, nb=d-chunk): frag = kb*8+nb
    const uint32_t Bv0 = sb + VF_OFF + (uint32_t)wid * (8 * KFB)
                       + (uint32_t)((lane >> 2) & 3) * 8 + (uint32_t)(lane >> 4) * 4
                       + (uint32_t)((lane & 3) * 2) * KFB;
    const uint32_t Bv1 = Bv0 + KFB;
    const float* kg = kbase + (wid * 8 + (lane >> 2)) * HDIM + (lane & 3) * 16;
    const float* vg = vbase + (wid * 8 + (lane >> 2)) * HDIM + (lane & 3) * 16;

    // ---- consumer bases ----
    const uint32_t kB = sb + KF_OFF + (uint32_t)lane * 8;
    const uint32_t vB = sb + VF_OFF + (uint32_t)lane * 8;
    const uint32_t Pw = sb + PF_OFF + (uint32_t)wid * 4096;
    const uint32_t swz = (uint32_t)((g >> 1) & 3);
    const uint32_t pA  = Pw + (uint32_t)(g * 4 + (t ^ swz)) * 16;
    const uint32_t pxz = Pw + (uint32_t)(g * 4 + (((2 * t) & 3) ^ swz)) * 16
                       + (uint32_t)(t >> 1) * 8;
    const uint32_t pyw = Pw + (uint32_t)(g * 4 + (((2 * t + 1) & 3) ^ swz)) * 16
                       + (uint32_t)(t >> 1) * 8;

    // q spatial coords
    const int qrow0 = qt * 128 + wid * 16 + g;
    const int qi0 = qrow0 >> 5,       qj0 = qrow0 & 31;
    const int qi1 = (qrow0 + 8) >> 5, qj1 = (qrow0 + 8) & 31;

    float4 o[8];
#pragma unroll
    for (int nt = 0; nt < 8; nt++) o[nt] = make_float4(0.f, 0.f, 0.f, 0.f);
    float m0 = -INFINITY, m1 = -INFINITY, l0 = 0.f, l1 = 0.f;

    for (int kt = 0; kt < 16; kt++) {
        __syncthreads();   // all warps done reading Kf/Vf of previous tile

        // ---- produce K and V fragments for this tile ----
        const float* kgp = kg + kt * 64 * HDIM;
        const float* vgp = vg + kt * 64 * HDIM;
#pragma unroll
        for (int i = 0; i < 4; i++) {
            const float4 k4 = *(const float4*)(kgp + 4 * i);
            const uint32_t bk = (i < 2) ? Bk0 : Bk1;
            const uint32_t so = (i & 1) * 4;
            sts32(bk + 0  + so, f2tf32(k4.x));
            sts32(bk + 8  + so, f2tf32(k4.y));
            sts32(bk + 16 + so, f2tf32(k4.z));
            sts32(bk + 24 + so, f2tf32(k4.w));
            const float4 v4 = *(const float4*)(vgp + 4 * i);
            const uint32_t bv = (i < 2) ? Bv0 : Bv1;
            const uint32_t vo = (i & 1) * 128;   // (4*(i&1)+j)*32
            sts32(bv + vo + 0,  f2tf32(v4.x));
            sts32(bv + vo + 32, f2tf32(v4.y));
            sts32(bv + vo + 64, f2tf32(v4.z));
            sts32(bv + vo + 96, f2tf32(v4.w));
        }
        __syncthreads();

        // ---- S = Q K^T : A from regs, B via LDS.64 ----
        float4 s[8];
#pragma unroll
        for (int nt = 0; nt < 8; nt++) s[nt] = make_float4(0.f, 0.f, 0.f, 0.f);
#pragma unroll
        for (int ks = 0; ks < 8; ks++) {
#pragma unroll
            for (int nt = 0; nt < 8; nt++) {
                uint32_t b0, b1;
                lds64(b0, b1, kB + (uint32_t)(nt * 8 + ks) * KFB);
                mma8(s[nt], qf[ks][0], qf[ks][1], qf[ks][2], qf[ks][3], b0, b1);
            }
        }

        // ---- bias + row max ----
        float mx0 = -INFINITY, mx1 = -INFINITY;
#pragma unroll
        for (int nt = 0; nt < 8; nt++) {
            const int col0 = kt * 64 + nt * 8 + 2 * t;
            const int ki = col0 >> 5;
            const int kj = col0 & 31;
            s[nt].x += __ldg(&rel_bias[((qi0 - ki + 31) * 63 + (qj0 - kj + 31)) * NHEAD + h]);
            s[nt].y += __ldg(&rel_bias[((qi0 - ki + 31) * 63 + (qj0 - kj + 30)) * NHEAD + h]);
            s[nt].z += __ldg(&rel_bias[((qi1 - ki + 31) * 63 + (qj1 - kj + 31)) * NHEAD + h]);
            s[nt].w += __ldg(&rel_bias[((qi1 - ki + 31) * 63 + (qj1 - kj + 30)) * NHEAD + h]);
            mx0 = fmaxf(mx0, fmaxf(s[nt].x, s[nt].y));
            mx1 = fmaxf(mx1, fmaxf(s[nt].z, s[nt].w));
        }
        mx0 = fmaxf(mx0, __shfl_xor_sync(0xffffffffu, mx0, 1));
        mx0 = fmaxf(mx0, __shfl_xor_sync(0xffffffffu, mx0, 2));
        mx1 = fmaxf(mx1, __shfl_xor_sync(0xffffffffu, mx1, 1));
        mx1 = fmaxf(mx1, __shfl_xor_sync(0xffffffffu, mx1, 2));

        const float mn0 = fmaxf(m0, mx0);
        const float mn1 = fmaxf(m1, mx1);
        const float al0 = __expf(m0 - mn0);
        const float al1 = __expf(m1 - mn1);
        float rs0 = 0.f, rs1 = 0.f;
#pragma unroll
        for (int nt = 0; nt < 8; nt++) {
            s[nt].x = __expf(s[nt].x - mn0);
            s[nt].y = __expf(s[nt].y - mn0);
            s[nt].z = __expf(s[nt].z - mn1);
            s[nt].w = __expf(s[nt].w - mn1);
            rs0 += s[nt].x + s[nt].y;
            rs1 += s[nt].z + s[nt].w;
            o[nt].x *= al0; o[nt].y *= al0;
            o[nt].z *= al1; o[nt].w *= al1;
        }
        rs0 += __shfl_xor_sync(0xffffffffu, rs0, 1);
        rs0 += __shfl_xor_sync(0xffffffffu, rs0, 2);
        rs1 += __shfl_xor_sync(0xffffffffu, rs1, 1);
        rs1 += __shfl_xor_sync(0xffffffffu, rs1, 2);
        l0 = l0 * al0 + rs0; m0 = mn0;
        l1 = l1 * al1 + rs1; m1 = mn1;

        // ---- P -> per-warp fragment smem (swizzled, conflict-free) ----
#pragma unroll
        for (int nt = 0; nt < 8; nt++) {
            sts32(pxz + nt * 512,     f2tf32(s[nt].x));
            sts32(pxz + nt * 512 + 4, f2tf32(s[nt].z));
            sts32(pyw + nt * 512,     f2tf32(s[nt].y));
            sts32(pyw + nt * 512 + 4, f2tf32(s[nt].w));
        }
        __syncwarp();

        // ---- O += P V : A via LDS.128, B via LDS.64 ----
#pragma unroll
        for (int ks = 0; ks < 8; ks++) {
            uint32_t pa[4];
            lds128(pa, pA + ks * 512);
#pragma unroll
            for (int nt = 0; nt < 8; nt++) {
                uint32_t b0, b1;
                lds64(b0, b1, vB + (uint32_t)(ks * 8 + nt) * KFB);
                mma8(o[nt], pa[0], pa[1], pa[2], pa[3], b0, b1);
            }
        }
        __syncwarp();   // PV reads done before next tile's P stores
    }

    // ---- epilogue ----
    const float inv0 = 1.f / l0;
    const float inv1 = 1.f / l1;
    float* out0 = out + (size_t)(b * NTOK + qrow0) * CDIM + h * HDIM;
    float* out1 = out + (size_t)(b * NTOK + qrow0 + 8) * CDIM + h * HDIM;
#pragma unroll
    for (int nt = 0; nt < 8; nt++) {
        const int dd = nt * 8 + 2 * t;
        *(float2*)(out0 + dd) = make_float2(o[nt].x * inv0, o[nt].y * inv0);
        *(float2*)(out1 + dd) = make_float2(o[nt].z * inv1, o[nt].w * inv1);
    }
}

// ============================================================================
extern "C" void kernel_launch(void* const* d_in, const int* in_sizes, int n_in,
                              void* d_out, int out_size)
{
    const float* x        = (const float*)d_in[0];
    const float* Wq       = (const float*)d_in[1];
    const float* bq       = (const float*)d_in[2];
    const float* Wkv      = (const float*)d_in[3];
    const float* bkv      = (const float*)d_in[4];
    const float* rel_bias = (const float*)d_in[5];
    float* out = (float*)d_out;

    qkv_tc<<<dim3(NTOTC / 128, MROWS / 128), 256>>>(x, Wq, bq, Wkv, bkv);

    cudaFuncSetAttribute(flash_tc, cudaFuncAttributeMaxDynamicSharedMemorySize,
                         FL_BYTES);
    flash_tc<<<dim3(8, BATCH * NHEAD), 256, FL_BYTES>>>(rel_bias, out);
}